// round 12
// baseline (speedup 1.0000x reference)
#include <cuda_runtime.h>
#include <cuda_fp16.h>
#include <math.h>
#include <stdint.h>

#define MTOT 32768
#define DD   1024

// ---------------- device scratch (no allocations allowed) ----------------
__device__ __align__(1024) __half g_Sh0[MTOT * DD];
__device__ __align__(1024) __half g_Sl0[MTOT * DD];
__device__ __align__(1024) __half g_Sh1[MTOT * DD];
__device__ __align__(1024) __half g_Sl1[MTOT * DD];
__device__ __align__(1024) __half g_Wh[6 * DD * DD];
__device__ __align__(1024) __half g_Wl[6 * DD * DD];
__device__ float g_H[MTOT * DD];
__device__ float g_Y[MTOT * DD];   // also reused as lb@la scratch during prep

// ------------------------------ helpers ----------------------------------
__device__ __forceinline__ uint32_t s2u(const void* p) {
    uint32_t a;
    asm("{ .reg .u64 t; cvta.to.shared.u64 t, %1; cvt.u32.u64 %0, t; }" : "=r"(a) : "l"(p));
    return a;
}
__device__ __forceinline__ void cpa(uint32_t s, const void* g) {
    asm volatile("cp.async.cg.shared.global [%0], [%1], 16;" :: "r"(s), "l"(g) : "memory");
}
__device__ __forceinline__ void ldsm4(uint32_t* r, uint32_t a) {
    asm volatile("ldmatrix.sync.aligned.m8n8.x4.shared.b16 {%0,%1,%2,%3}, [%4];"
                 : "=r"(r[0]), "=r"(r[1]), "=r"(r[2]), "=r"(r[3]) : "r"(a));
}
__device__ __forceinline__ void mma_f32(float* c, const uint32_t* a, const uint32_t* b) {
    asm volatile(
        "mma.sync.aligned.m16n8k16.row.col.f32.f16.f16.f32 "
        "{%0,%1,%2,%3}, {%4,%5,%6,%7}, {%8,%9}, {%0,%1,%2,%3};"
        : "+f"(c[0]), "+f"(c[1]), "+f"(c[2]), "+f"(c[3])
        : "r"(a[0]), "r"(a[1]), "r"(a[2]), "r"(a[3]), "r"(b[0]), "r"(b[1]));
}
__device__ __forceinline__ void mma_f16(uint32_t* c, const uint32_t* a, const uint32_t* b) {
    asm volatile(
        "mma.sync.aligned.m16n8k16.row.col.f16.f16.f16.f16 "
        "{%0,%1}, {%2,%3,%4,%5}, {%6,%7}, {%0,%1};"
        : "+r"(c[0]), "+r"(c[1])
        : "r"(a[0]), "r"(a[1]), "r"(a[2]), "r"(a[3]), "r"(b[0]), "r"(b[1]));
}
__device__ __forceinline__ uint32_t h2u(float a, float b) {
    __half2 h = __floats2half2_rn(a, b);
    return *(uint32_t*)&h;
}
__device__ __forceinline__ float hres(float a) {   // residual after fp16 rounding
    return a - __half2float(__float2half_rn(a));
}
__device__ __forceinline__ uint32_t swz(uint32_t o) { return o ^ ((o >> 3) & 0x70); }

// ---------------- prep 1: M = lb @ la  (rank-32 outer product) -----------
__global__ void __launch_bounds__(256) k_loramm(const float* __restrict__ lb,
                                                const float* __restrict__ la,
                                                float* __restrict__ M) {
    extern __shared__ float sm[];
    float* sla = sm;                 // 32*1024
    float* slb = sm + 32 * 1024;     // 16*32
    int l = blockIdx.x >> 6, ot = blockIdx.x & 63;
    const float* laL = la + (size_t)l * 32 * 1024;
    const float* lbL = lb + (size_t)l * 1024 * 32 + ot * 16 * 32;
    for (int i = threadIdx.x; i < 32 * 1024 / 4; i += 256)
        ((float4*)sla)[i] = ((const float4*)laL)[i];
    for (int i = threadIdx.x; i < 16 * 32 / 4; i += 256)
        ((float4*)slb)[i] = ((const float4*)lbL)[i];
    __syncthreads();
    float acc[16][4];
#pragma unroll
    for (int o = 0; o < 16; o++)
#pragma unroll
        for (int j = 0; j < 4; j++) acc[o][j] = 0.f;
    int i0 = threadIdx.x * 4;
#pragma unroll
    for (int r = 0; r < 32; r++) {
        float4 la4 = *(float4*)&sla[r * 1024 + i0];
#pragma unroll
        for (int o = 0; o < 16; o++) {
            float b = slb[o * 32 + r];
            acc[o][0] += b * la4.x; acc[o][1] += b * la4.y;
            acc[o][2] += b * la4.z; acc[o][3] += b * la4.w;
        }
    }
#pragma unroll
    for (int o = 0; o < 16; o++) {
        float4 v = {acc[o][0], acc[o][1], acc[o][2], acc[o][3]};
        *(float4*)&M[((size_t)l * 1024 + ot * 16 + o) * 1024 + i0] = v;
    }
}

// ---------------- prep 2: dequant + lora fold -> fp16 hi/lo --------------
__global__ void k_prepw(const int* __restrict__ q, const float* __restrict__ s,
                        const float* __restrict__ M) {
    int idx = blockIdx.x * 256 + threadIdx.x;     // over 6*1024*1024
    int i = idx & 1023, row = idx >> 10;          // row = l*1024 + o
    float w = ((float)q[idx] * (1.0f / 7.5f) - 1.0f) * s[(size_t)row * 64 + (i >> 4)]
            + M[idx];
    g_Wh[idx] = __float2half_rn(w);
    g_Wl[idx] = __float2half_rn(hres(w));
}

// x -> fp16 splits into buffer 0 (no fp32 copy; x used directly as residual)
__global__ void k_convert(const float* __restrict__ X) {
    int t = blockIdx.x * 256 + threadIdx.x;
    int m = t >> 8, c4 = (t & 255) * 4;
    float4 v = ((const float4*)X)[t];
    uint2 uh = {h2u(v.x, v.y), h2u(v.z, v.w)};
    uint2 ul = {h2u(hres(v.x), hres(v.y)), h2u(hres(v.z), hres(v.w))};
    *(uint2*)&g_Sh0[(size_t)m * DD + c4] = uh;
    *(uint2*)&g_Sl0[(size_t)m * DD + c4] = ul;
}

// ---------------- LayerNorm + exact GELU -> fp16 splits ------------------
__global__ void __launch_bounds__(256) k_lngelu(const float* __restrict__ Y,
                                                const float* __restrict__ g,
                                                const float* __restrict__ b,
                                                __half* __restrict__ oh,
                                                __half* __restrict__ ol) {
    int warp = threadIdx.x >> 5, lane = threadIdx.x & 31;
    int t = blockIdx.x * 8 + warp;
    const float4* row = (const float4*)(Y + (size_t)t * DD);
    float4 v[8];
    float s = 0.f, sq = 0.f;
#pragma unroll
    for (int i = 0; i < 8; i++) {
        v[i] = row[i * 32 + lane];
        s  += v[i].x + v[i].y + v[i].z + v[i].w;
        sq += v[i].x * v[i].x + v[i].y * v[i].y + v[i].z * v[i].z + v[i].w * v[i].w;
    }
#pragma unroll
    for (int o = 16; o > 0; o >>= 1) {
        s  += __shfl_xor_sync(0xffffffffu, s, o);
        sq += __shfl_xor_sync(0xffffffffu, sq, o);
    }
    float mu  = s * (1.f / 1024.f);
    float var = sq * (1.f / 1024.f) - mu * mu;
    float rs  = rsqrtf(var + 1e-5f);
#pragma unroll
    for (int i = 0; i < 8; i++) {
        int c4 = (i * 32 + lane) * 4;
        float xv[4] = {v[i].x, v[i].y, v[i].z, v[i].w};
        float yv[4];
#pragma unroll
        for (int j = 0; j < 4; j++) {
            float xn = (xv[j] - mu) * rs * g[c4 + j] + b[c4 + j];
            yv[j] = 0.5f * xn * (1.f + erff(xn * 0.70710678118654752f));
        }
        uint2 uh = {h2u(yv[0], yv[1]), h2u(yv[2], yv[3])};
        uint2 ul = {h2u(hres(yv[0]), hres(yv[1])), h2u(hres(yv[2]), hres(yv[3]))};
        *(uint2*)&oh[(size_t)t * DD + c4] = uh;
        *(uint2*)&ol[(size_t)t * DD + c4] = ul;
    }
}

// ----------- MAIN GEMM: 256 thr, CTA 128x256, warp 64x64, 2-stage --------
// main term fp32-accum; both corrections (Ah*Wl + Al*Wh) in fp16 accum.
// MODE 0: dst = D + bias ; MODE 1: dst = D + bias + res, splits -> ShO/SlO
template <int MODE>
__global__ void __launch_bounds__(256, 1) k_gmain(
    const __half* __restrict__ Ah_g, const __half* __restrict__ Al_g,
    const __half* __restrict__ Bh_g, const __half* __restrict__ Bl_g,
    const float* __restrict__ bias, const float* __restrict__ res,
    float* __restrict__ dst,
    __half* __restrict__ ShO, __half* __restrict__ SlO)
{
    constexpr int NKT   = 16;
    constexpr int OF_AL = 16384;
    constexpr int OF_BH = 32768;
    constexpr int OF_BL = 65536;
    constexpr int STG   = 98304;
    constexpr int RB    = DD * 2;

    extern __shared__ char smem[];
    uint32_t ab = (s2u(smem) + 1023u) & ~1023u;

    int tid = threadIdx.x, wid = tid >> 5, lane = tid & 31;
    int n0 = blockIdx.x * 256;
    int m0 = blockIdx.y * 128;
    int wm = wid & 1, wn = wid >> 1;                    // 2 x 4 warps, 64x64 tiles

    auto ldst = [&](int kt, int s) {
        uint32_t base = ab + s * STG;
        size_t kb = (size_t)kt * 128;
        const char* pAh = (const char*)Ah_g + (size_t)m0 * RB + kb;
        const char* pAl = (const char*)Al_g + (size_t)m0 * RB + kb;
        const char* pBh = (const char*)Bh_g + (size_t)n0 * RB + kb;
        const char* pBl = (const char*)Bl_g + (size_t)n0 * RB + kb;
#pragma unroll
        for (int j = 0; j < 4; j++) {
            int c = j * 256 + tid, row = c >> 3, qq = c & 7;
            uint32_t off = swz((uint32_t)(row * 128 + qq * 16));
            cpa(base + off, pAh + (size_t)row * RB + qq * 16);
            cpa(base + OF_AL + off, pAl + (size_t)row * RB + qq * 16);
        }
#pragma unroll
        for (int j = 0; j < 8; j++) {
            int c = j * 256 + tid, row = c >> 3, qq = c & 7;
            uint32_t off = swz((uint32_t)(row * 128 + qq * 16));
            cpa(base + OF_BH + off, pBh + (size_t)row * RB + qq * 16);
            cpa(base + OF_BL + off, pBl + (size_t)row * RB + qq * 16);
        }
        asm volatile("cp.async.commit_group;" ::: "memory");
    };

    float acc[4][8][4];
    uint32_t corr[4][8][2];
#pragma unroll
    for (int i = 0; i < 4; i++)
#pragma unroll
        for (int j = 0; j < 8; j++) {
#pragma unroll
            for (int q = 0; q < 4; q++) acc[i][j][q] = 0.f;
            corr[i][j][0] = 0u; corr[i][j][1] = 0u;
        }

    ldst(0, 0);

    for (int k = 0; k < NKT; k++) {
        const int s = k & 1;
        asm volatile("cp.async.wait_group 0;" ::: "memory");
        __syncthreads();
        if (k + 1 < NKT) ldst(k + 1, s ^ 1);
        uint32_t aB = ab + s * STG;
        uint32_t bB = aB + OF_BH;
#pragma unroll
        for (int kc = 0; kc < 4; kc++) {
            uint32_t bfr[8][2];
            uint32_t nbyte = (uint32_t)(kc * 32 + (((lane >> 3) & 1) << 4));
            uint32_t abyte = (uint32_t)(kc * 32 + ((lane >> 4) << 4));
            // ---- phase 1: B-high frags; main fp32 + Al*Wh correction ----
#pragma unroll
            for (int nh = 0; nh < 4; nh++) {
                uint32_t nrow = (uint32_t)(wn * 64 + nh * 16 + ((lane >> 4) << 3) + (lane & 7));
                uint32_t off = swz(nrow * 128 + nbyte);
                uint32_t r[4];
                ldsm4(r, bB + off);
                bfr[nh * 2][0] = r[0]; bfr[nh * 2][1] = r[1];
                bfr[nh * 2 + 1][0] = r[2]; bfr[nh * 2 + 1][1] = r[3];
            }
#pragma unroll
            for (int mg = 0; mg < 4; mg++) {
                uint32_t ah[4], al[4];
                uint32_t off = swz((uint32_t)((wm * 64 + mg * 16 + (lane & 15)) * 128) + abyte);
                ldsm4(ah, aB + off);
                ldsm4(al, aB + OF_AL + off);
#pragma unroll
                for (int ng = 0; ng < 8; ng++) {
                    mma_f32(acc[mg][ng], ah, bfr[ng]);
                    mma_f16(corr[mg][ng], al, bfr[ng]);
                }
            }
            // ---- phase 2: B-low frags (reuse regs); Ah*Wl correction ----
#pragma unroll
            for (int nh = 0; nh < 4; nh++) {
                uint32_t nrow = (uint32_t)(wn * 64 + nh * 16 + ((lane >> 4) << 3) + (lane & 7));
                uint32_t off = swz(nrow * 128 + nbyte);
                uint32_t r[4];
                ldsm4(r, aB + OF_BL + off);
                bfr[nh * 2][0] = r[0]; bfr[nh * 2][1] = r[1];
                bfr[nh * 2 + 1][0] = r[2]; bfr[nh * 2 + 1][1] = r[3];
            }
#pragma unroll
            for (int mg = 0; mg < 4; mg++) {
                uint32_t ah[4];
                uint32_t off = swz((uint32_t)((wm * 64 + mg * 16 + (lane & 15)) * 128) + abyte);
                ldsm4(ah, aB + off);
#pragma unroll
                for (int ng = 0; ng < 8; ng++)
                    mma_f16(corr[mg][ng], ah, bfr[ng]);
            }
        }
    }

    // ------------------------------- epilogue ----------------------------
    int t4 = lane >> 2, t2 = (lane & 3) * 2;
#pragma unroll
    for (int mg = 0; mg < 4; mg++)
#pragma unroll
        for (int ng = 0; ng < 8; ng++) {
            float* c = acc[mg][ng];
            int col = n0 + wn * 64 + ng * 8 + t2;
#pragma unroll
            for (int hh = 0; hh < 2; hh++) {
                int row = m0 + wm * 64 + mg * 16 + t4 + hh * 8;
                __half2 ch = *(__half2*)&corr[mg][ng][hh];
                float2 cf = __half22float2(ch);
                float2 b2 = *(const float2*)&bias[col];
                float v0 = c[hh * 2] + cf.x + b2.x;
                float v1 = c[hh * 2 + 1] + cf.y + b2.y;
                if (MODE == 1) {
                    float2 r2 = *(const float2*)&res[(size_t)row * DD + col];
                    v0 += r2.x; v1 += r2.y;
                }
                float2 o2 = {v0, v1};
                *(float2*)&dst[(size_t)row * DD + col] = o2;
                if (MODE == 1) {
                    *(uint32_t*)&ShO[(size_t)row * DD + col] = h2u(v0, v1);
                    *(uint32_t*)&SlO[(size_t)row * DD + col] = h2u(hres(v0), hres(v1));
                }
            }
        }
}

// ------------------------------- launch ----------------------------------
extern "C" void kernel_launch(void* const* d_in, const int* in_sizes, int n_in,
                              void* d_out, int out_size) {
    const float* x   = (const float*)d_in[0];
    const int*   q   = (const int*)d_in[1];
    const float* sc  = (const float*)d_in[2];
    const float* bia = (const float*)d_in[3];
    const float* la  = (const float*)d_in[4];
    const float* lbw = (const float*)d_in[5];
    const float* gam = (const float*)d_in[6];
    const float* bet = (const float*)d_in[7];
    float* out = (float*)d_out;

    __half *Wh, *Wl, *Sh[2], *Sl[2];
    float *H, *Y;
    cudaGetSymbolAddress((void**)&Wh, g_Wh);
    cudaGetSymbolAddress((void**)&Wl, g_Wl);
    cudaGetSymbolAddress((void**)&Sh[0], g_Sh0);
    cudaGetSymbolAddress((void**)&Sl[0], g_Sl0);
    cudaGetSymbolAddress((void**)&Sh[1], g_Sh1);
    cudaGetSymbolAddress((void**)&Sl[1], g_Sl1);
    cudaGetSymbolAddress((void**)&H,  g_H);
    cudaGetSymbolAddress((void**)&Y,  g_Y);

    const int SM_MAIN = 1024 + 2 * 98304;                 // 197632
    const int SM_MM   = (32 * 1024 + 16 * 32) * 4;        // 133120
    cudaFuncSetAttribute(k_gmain<0>, cudaFuncAttributeMaxDynamicSharedMemorySize, SM_MAIN);
    cudaFuncSetAttribute(k_gmain<1>, cudaFuncAttributeMaxDynamicSharedMemorySize, SM_MAIN);
    cudaFuncSetAttribute(k_loramm, cudaFuncAttributeMaxDynamicSharedMemorySize, SM_MM);

    k_loramm<<<6 * 64, 256, SM_MM>>>(lbw, la, Y);
    k_prepw<<<6 * DD * DD / 256, 256>>>(q, sc, Y);
    k_convert<<<MTOT * DD / 4 / 256, 256>>>(x);

    int p = 0;
    for (int blk = 0; blk < 3; ++blk) {
        int l0 = 2 * blk, l1 = 2 * blk + 1;
        k_gmain<0><<<dim3(4, MTOT / 128), 256, SM_MAIN>>>(
            Sh[p], Sl[p], Wh + (size_t)l0 * DD * DD, Wl + (size_t)l0 * DD * DD,
            bia + l0 * DD, nullptr, Y, nullptr, nullptr);
        k_lngelu<<<MTOT / 8, 256>>>(Y, gam + blk * DD, bet + blk * DD, Sh[p], Sl[p]);
        const float* resp = (blk == 0) ? x : H;
        float* dst = (blk == 2) ? out : H;
        k_gmain<1><<<dim3(4, MTOT / 128), 256, SM_MAIN>>>(
            Sh[p], Sl[p], Wh + (size_t)l1 * DD * DD, Wl + (size_t)l1 * DD * DD,
            bia + l1 * DD, resp, dst, Sh[p ^ 1], Sl[p ^ 1]);
        p ^= 1;
    }
}

// round 13
// speedup vs baseline: 1.0174x; 1.0174x over previous
#include <cuda_runtime.h>
#include <cuda_fp16.h>
#include <math.h>
#include <stdint.h>

#define MTOT 32768
#define DD   1024

// ---------------- device scratch (no allocations allowed) ----------------
__device__ __align__(1024) __half g_Sh0[MTOT * DD];
__device__ __align__(1024) __half g_Sl0[MTOT * DD];
__device__ __align__(1024) __half g_Sh1[MTOT * DD];
__device__ __align__(1024) __half g_Sl1[MTOT * DD];
__device__ __align__(1024) __half g_Wh[6 * DD * DD];
__device__ __align__(1024) __half g_Wl[6 * DD * DD];
__device__ float g_H[MTOT * DD];
__device__ float g_Y[MTOT * DD];   // also reused as lb@la scratch during prep

// ------------------------------ helpers ----------------------------------
__device__ __forceinline__ uint32_t s2u(const void* p) {
    uint32_t a;
    asm("{ .reg .u64 t; cvta.to.shared.u64 t, %1; cvt.u32.u64 %0, t; }" : "=r"(a) : "l"(p));
    return a;
}
__device__ __forceinline__ void cpa(uint32_t s, const void* g) {
    asm volatile("cp.async.cg.shared.global [%0], [%1], 16;" :: "r"(s), "l"(g) : "memory");
}
__device__ __forceinline__ void ldsm4(uint32_t* r, uint32_t a) {
    asm volatile("ldmatrix.sync.aligned.m8n8.x4.shared.b16 {%0,%1,%2,%3}, [%4];"
                 : "=r"(r[0]), "=r"(r[1]), "=r"(r[2]), "=r"(r[3]) : "r"(a));
}
__device__ __forceinline__ void mma_f32(float* c, const uint32_t* a, const uint32_t* b) {
    asm volatile(
        "mma.sync.aligned.m16n8k16.row.col.f32.f16.f16.f32 "
        "{%0,%1,%2,%3}, {%4,%5,%6,%7}, {%8,%9}, {%0,%1,%2,%3};"
        : "+f"(c[0]), "+f"(c[1]), "+f"(c[2]), "+f"(c[3])
        : "r"(a[0]), "r"(a[1]), "r"(a[2]), "r"(a[3]), "r"(b[0]), "r"(b[1]));
}
__device__ __forceinline__ uint32_t h2u(float a, float b) {
    __half2 h = __floats2half2_rn(a, b);
    return *(uint32_t*)&h;
}
__device__ __forceinline__ float hres(float a) {   // residual after fp16 rounding
    return a - __half2float(__float2half_rn(a));
}
__device__ __forceinline__ uint32_t swz(uint32_t o) { return o ^ ((o >> 3) & 0x70); }

// ---------------- prep 1: M = lb @ la  (rank-32 outer product) -----------
__global__ void __launch_bounds__(256) k_loramm(const float* __restrict__ lb,
                                                const float* __restrict__ la,
                                                float* __restrict__ M) {
    extern __shared__ float sm[];
    float* sla = sm;                 // 32*1024
    float* slb = sm + 32 * 1024;     // 16*32
    int l = blockIdx.x >> 6, ot = blockIdx.x & 63;
    const float* laL = la + (size_t)l * 32 * 1024;
    const float* lbL = lb + (size_t)l * 1024 * 32 + ot * 16 * 32;
    for (int i = threadIdx.x; i < 32 * 1024 / 4; i += 256)
        ((float4*)sla)[i] = ((const float4*)laL)[i];
    for (int i = threadIdx.x; i < 16 * 32 / 4; i += 256)
        ((float4*)slb)[i] = ((const float4*)lbL)[i];
    __syncthreads();
    float acc[16][4];
#pragma unroll
    for (int o = 0; o < 16; o++)
#pragma unroll
        for (int j = 0; j < 4; j++) acc[o][j] = 0.f;
    int i0 = threadIdx.x * 4;
#pragma unroll
    for (int r = 0; r < 32; r++) {
        float4 la4 = *(float4*)&sla[r * 1024 + i0];
#pragma unroll
        for (int o = 0; o < 16; o++) {
            float b = slb[o * 32 + r];
            acc[o][0] += b * la4.x; acc[o][1] += b * la4.y;
            acc[o][2] += b * la4.z; acc[o][3] += b * la4.w;
        }
    }
#pragma unroll
    for (int o = 0; o < 16; o++) {
        float4 v = {acc[o][0], acc[o][1], acc[o][2], acc[o][3]};
        *(float4*)&M[((size_t)l * 1024 + ot * 16 + o) * 1024 + i0] = v;
    }
}

// ---------------- prep 2: dequant + lora fold -> fp16 hi/lo --------------
__global__ void k_prepw(const int* __restrict__ q, const float* __restrict__ s,
                        const float* __restrict__ M) {
    int idx = blockIdx.x * 256 + threadIdx.x;     // over 6*1024*1024
    int i = idx & 1023, row = idx >> 10;          // row = l*1024 + o
    float w = ((float)q[idx] * (1.0f / 7.5f) - 1.0f) * s[(size_t)row * 64 + (i >> 4)]
            + M[idx];
    g_Wh[idx] = __float2half_rn(w);
    g_Wl[idx] = __float2half_rn(hres(w));
}

// x -> fp16 splits into buffer 0 (x itself used as block-0 residual)
__global__ void k_convert(const float* __restrict__ X) {
    int t = blockIdx.x * 256 + threadIdx.x;
    int m = t >> 8, c4 = (t & 255) * 4;
    float4 v = ((const float4*)X)[t];
    uint2 uh = {h2u(v.x, v.y), h2u(v.z, v.w)};
    uint2 ul = {h2u(hres(v.x), hres(v.y)), h2u(hres(v.z), hres(v.w))};
    *(uint2*)&g_Sh0[(size_t)m * DD + c4] = uh;
    *(uint2*)&g_Sl0[(size_t)m * DD + c4] = ul;
}

// ---------------- LayerNorm + exact GELU -> fp16 splits ------------------
__global__ void __launch_bounds__(256) k_lngelu(const float* __restrict__ Y,
                                                const float* __restrict__ g,
                                                const float* __restrict__ b,
                                                __half* __restrict__ oh,
                                                __half* __restrict__ ol) {
    int warp = threadIdx.x >> 5, lane = threadIdx.x & 31;
    int t = blockIdx.x * 8 + warp;
    const float4* row = (const float4*)(Y + (size_t)t * DD);
    float4 v[8];
    float s = 0.f, sq = 0.f;
#pragma unroll
    for (int i = 0; i < 8; i++) {
        v[i] = row[i * 32 + lane];
        s  += v[i].x + v[i].y + v[i].z + v[i].w;
        sq += v[i].x * v[i].x + v[i].y * v[i].y + v[i].z * v[i].z + v[i].w * v[i].w;
    }
#pragma unroll
    for (int o = 16; o > 0; o >>= 1) {
        s  += __shfl_xor_sync(0xffffffffu, s, o);
        sq += __shfl_xor_sync(0xffffffffu, sq, o);
    }
    float mu  = s * (1.f / 1024.f);
    float var = sq * (1.f / 1024.f) - mu * mu;
    float rs  = rsqrtf(var + 1e-5f);
#pragma unroll
    for (int i = 0; i < 8; i++) {
        int c4 = (i * 32 + lane) * 4;
        float xv[4] = {v[i].x, v[i].y, v[i].z, v[i].w};
        float yv[4];
#pragma unroll
        for (int j = 0; j < 4; j++) {
            float xn = (xv[j] - mu) * rs * g[c4 + j] + b[c4 + j];
            yv[j] = 0.5f * xn * (1.f + erff(xn * 0.70710678118654752f));
        }
        uint2 uh = {h2u(yv[0], yv[1]), h2u(yv[2], yv[3])};
        uint2 ul = {h2u(hres(yv[0]), hres(yv[1])), h2u(hres(yv[2]), hres(yv[3]))};
        *(uint2*)&oh[(size_t)t * DD + c4] = uh;
        *(uint2*)&ol[(size_t)t * DD + c4] = ul;
    }
}

// ------- MAIN GEMM: 512 thr, CTA 128x256, warp tile 64x32, 2-stage -------
// D = A[128,1024] @ B[256,1024]^T, 3-term fp16 split, fp32 accum.
// MODE 0: dst = D + bias ; MODE 1: dst = D + bias + res, splits -> ShO/SlO
template <int MODE>
__global__ void __launch_bounds__(512, 1) k_gmain(
    const __half* __restrict__ Ah_g, const __half* __restrict__ Al_g,
    const __half* __restrict__ Bh_g, const __half* __restrict__ Bl_g,
    const float* __restrict__ bias, const float* __restrict__ res,
    float* __restrict__ dst,
    __half* __restrict__ ShO, __half* __restrict__ SlO)
{
    constexpr int NKT   = 16;
    constexpr int OF_AL = 16384;
    constexpr int OF_BH = 32768;
    constexpr int OF_BL = 65536;
    constexpr int STG   = 98304;
    constexpr int RB    = DD * 2;

    extern __shared__ char smem[];
    uint32_t ab = (s2u(smem) + 1023u) & ~1023u;

    int tid = threadIdx.x, wid = tid >> 5, lane = tid & 31;
    int n0 = blockIdx.x * 256;
    int m0 = blockIdx.y * 128;
    int wm = wid & 1, wn = wid >> 1;                    // 2 x 8 warps, 64x32 tiles

    auto ldst = [&](int kt, int s) {
        uint32_t base = ab + s * STG;
        size_t kb = (size_t)kt * 128;
        const char* pAh = (const char*)Ah_g + (size_t)m0 * RB + kb;
        const char* pAl = (const char*)Al_g + (size_t)m0 * RB + kb;
        const char* pBh = (const char*)Bh_g + (size_t)n0 * RB + kb;
        const char* pBl = (const char*)Bl_g + (size_t)n0 * RB + kb;
#pragma unroll
        for (int j = 0; j < 2; j++) {                   // A: 128 rows x 8 chunks
            int c = j * 512 + tid, row = c >> 3, qq = c & 7;
            uint32_t off = swz((uint32_t)(row * 128 + qq * 16));
            cpa(base + off, pAh + (size_t)row * RB + qq * 16);
            cpa(base + OF_AL + off, pAl + (size_t)row * RB + qq * 16);
        }
#pragma unroll
        for (int j = 0; j < 4; j++) {                   // B: 256 rows x 8 chunks
            int c = j * 512 + tid, row = c >> 3, qq = c & 7;
            uint32_t off = swz((uint32_t)(row * 128 + qq * 16));
            cpa(base + OF_BH + off, pBh + (size_t)row * RB + qq * 16);
            cpa(base + OF_BL + off, pBl + (size_t)row * RB + qq * 16);
        }
        asm volatile("cp.async.commit_group;" ::: "memory");
    };

    float acc[4][4][4];
#pragma unroll
    for (int i = 0; i < 4; i++)
#pragma unroll
        for (int j = 0; j < 4; j++)
#pragma unroll
            for (int q = 0; q < 4; q++) acc[i][j][q] = 0.f;

    ldst(0, 0);

    for (int k = 0; k < NKT; k++) {
        const int s = k & 1;
        asm volatile("cp.async.wait_group 0;" ::: "memory");
        __syncthreads();
        if (k + 1 < NKT) ldst(k + 1, s ^ 1);
        uint32_t aB = ab + s * STG;
        uint32_t bB = aB + OF_BH;
#pragma unroll
        for (int kc = 0; kc < 4; kc++) {
            uint32_t bh[4][2], bl[4][2];
            uint32_t nbyte = (uint32_t)(kc * 32 + (((lane >> 3) & 1) << 4));
#pragma unroll
            for (int nh = 0; nh < 2; nh++) {
                uint32_t nrow = (uint32_t)(wn * 32 + nh * 16 + ((lane >> 4) << 3) + (lane & 7));
                uint32_t off = swz(nrow * 128 + nbyte);
                uint32_t r[4];
                ldsm4(r, bB + off);
                bh[nh * 2][0] = r[0]; bh[nh * 2][1] = r[1];
                bh[nh * 2 + 1][0] = r[2]; bh[nh * 2 + 1][1] = r[3];
                ldsm4(r, aB + OF_BL + off);
                bl[nh * 2][0] = r[0]; bl[nh * 2][1] = r[1];
                bl[nh * 2 + 1][0] = r[2]; bl[nh * 2 + 1][1] = r[3];
            }
            uint32_t abyte = (uint32_t)(kc * 32 + ((lane >> 4) << 4));
#pragma unroll
            for (int mg = 0; mg < 4; mg++) {
                uint32_t ah[4], al[4];
                uint32_t off = swz((uint32_t)((wm * 64 + mg * 16 + (lane & 15)) * 128) + abyte);
                ldsm4(ah, aB + off);
                ldsm4(al, aB + OF_AL + off);
#pragma unroll
                for (int ng = 0; ng < 4; ng++) {
                    mma_f32(acc[mg][ng], ah, bh[ng]);
                    mma_f32(acc[mg][ng], ah, bl[ng]);
                    mma_f32(acc[mg][ng], al, bh[ng]);
                }
            }
        }
    }

    // ------------------------------- epilogue ----------------------------
    int t4 = lane >> 2, t2 = (lane & 3) * 2;
#pragma unroll
    for (int mg = 0; mg < 4; mg++)
#pragma unroll
        for (int ng = 0; ng < 4; ng++) {
            float* c = acc[mg][ng];
            int col = n0 + wn * 32 + ng * 8 + t2;
#pragma unroll
            for (int hh = 0; hh < 2; hh++) {
                int row = m0 + wm * 64 + mg * 16 + t4 + hh * 8;
                float2 b2 = *(const float2*)&bias[col];
                float v0 = c[hh * 2] + b2.x, v1 = c[hh * 2 + 1] + b2.y;
                if (MODE == 1) {
                    float2 r2 = *(const float2*)&res[(size_t)row * DD + col];
                    v0 += r2.x; v1 += r2.y;
                }
                float2 o2 = {v0, v1};
                *(float2*)&dst[(size_t)row * DD + col] = o2;
                if (MODE == 1) {
                    *(uint32_t*)&ShO[(size_t)row * DD + col] = h2u(v0, v1);
                    *(uint32_t*)&SlO[(size_t)row * DD + col] = h2u(hres(v0), hres(v1));
                }
            }
        }
}

// ------------------------------- launch ----------------------------------
extern "C" void kernel_launch(void* const* d_in, const int* in_sizes, int n_in,
                              void* d_out, int out_size) {
    const float* x   = (const float*)d_in[0];
    const int*   q   = (const int*)d_in[1];
    const float* sc  = (const float*)d_in[2];
    const float* bia = (const float*)d_in[3];
    const float* la  = (const float*)d_in[4];
    const float* lbw = (const float*)d_in[5];
    const float* gam = (const float*)d_in[6];
    const float* bet = (const float*)d_in[7];
    float* out = (float*)d_out;

    __half *Wh, *Wl, *Sh[2], *Sl[2];
    float *H, *Y;
    cudaGetSymbolAddress((void**)&Wh, g_Wh);
    cudaGetSymbolAddress((void**)&Wl, g_Wl);
    cudaGetSymbolAddress((void**)&Sh[0], g_Sh0);
    cudaGetSymbolAddress((void**)&Sl[0], g_Sl0);
    cudaGetSymbolAddress((void**)&Sh[1], g_Sh1);
    cudaGetSymbolAddress((void**)&Sl[1], g_Sl1);
    cudaGetSymbolAddress((void**)&H,  g_H);
    cudaGetSymbolAddress((void**)&Y,  g_Y);

    const int SM_MAIN = 1024 + 2 * 98304;                 // 197632
    const int SM_MM   = (32 * 1024 + 16 * 32) * 4;        // 133120
    cudaFuncSetAttribute(k_gmain<0>, cudaFuncAttributeMaxDynamicSharedMemorySize, SM_MAIN);
    cudaFuncSetAttribute(k_gmain<1>, cudaFuncAttributeMaxDynamicSharedMemorySize, SM_MAIN);
    cudaFuncSetAttribute(k_loramm, cudaFuncAttributeMaxDynamicSharedMemorySize, SM_MM);

    k_loramm<<<6 * 64, 256, SM_MM>>>(lbw, la, Y);
    k_prepw<<<6 * DD * DD / 256, 256>>>(q, sc, Y);
    k_convert<<<MTOT * DD / 4 / 256, 256>>>(x);

    int p = 0;
    for (int blk = 0; blk < 3; ++blk) {
        int l0 = 2 * blk, l1 = 2 * blk + 1;
        k_gmain<0><<<dim3(4, MTOT / 128), 512, SM_MAIN>>>(
            Sh[p], Sl[p], Wh + (size_t)l0 * DD * DD, Wl + (size_t)l0 * DD * DD,
            bia + l0 * DD, nullptr, Y, nullptr, nullptr);
        k_lngelu<<<MTOT / 8, 256>>>(Y, gam + blk * DD, bet + blk * DD, Sh[p], Sl[p]);
        const float* resp = (blk == 0) ? x : H;
        float* dst = (blk == 2) ? out : H;
        k_gmain<1><<<dim3(4, MTOT / 128), 512, SM_MAIN>>>(
            Sh[p], Sl[p], Wh + (size_t)l1 * DD * DD, Wl + (size_t)l1 * DD * DD,
            bia + l1 * DD, resp, dst, Sh[p ^ 1], Sl[p ^ 1]);
        p ^= 1;
    }
}

// round 15
// speedup vs baseline: 1.0314x; 1.0137x over previous
#include <cuda_runtime.h>
#include <cuda_fp16.h>
#include <math.h>
#include <stdint.h>

#define MTOT 32768
#define DD   1024

// ---------------- device scratch (no allocations allowed) ----------------
__device__ __align__(1024) __half g_Sh0[MTOT * DD];
__device__ __align__(1024) __half g_Sl0[MTOT * DD];
__device__ __align__(1024) __half g_Sh1[MTOT * DD];
__device__ __align__(1024) __half g_Sl1[MTOT * DD];
__device__ __align__(1024) __half g_Wh[6 * DD * DD];
__device__ __align__(1024) __half g_Wl[6 * DD * DD];
__device__ float g_H[MTOT * DD];
__device__ float g_Y[MTOT * DD];   // also reused as lb@la scratch during prep

// ------------------------------ helpers ----------------------------------
__device__ __forceinline__ uint32_t s2u(const void* p) {
    uint32_t a;
    asm("{ .reg .u64 t; cvta.to.shared.u64 t, %1; cvt.u32.u64 %0, t; }" : "=r"(a) : "l"(p));
    return a;
}
__device__ __forceinline__ void cpa(uint32_t s, const void* g) {
    asm volatile("cp.async.cg.shared.global [%0], [%1], 16;" :: "r"(s), "l"(g) : "memory");
}
__device__ __forceinline__ void ldsm4(uint32_t* r, uint32_t a) {
    asm volatile("ldmatrix.sync.aligned.m8n8.x4.shared.b16 {%0,%1,%2,%3}, [%4];"
                 : "=r"(r[0]), "=r"(r[1]), "=r"(r[2]), "=r"(r[3]) : "r"(a));
}
__device__ __forceinline__ void mma_f32(float* c, const uint32_t* a, const uint32_t* b) {
    asm volatile(
        "mma.sync.aligned.m16n8k16.row.col.f32.f16.f16.f32 "
        "{%0,%1,%2,%3}, {%4,%5,%6,%7}, {%8,%9}, {%0,%1,%2,%3};"
        : "+f"(c[0]), "+f"(c[1]), "+f"(c[2]), "+f"(c[3])
        : "r"(a[0]), "r"(a[1]), "r"(a[2]), "r"(a[3]), "r"(b[0]), "r"(b[1]));
}
__device__ __forceinline__ uint32_t h2u(float a, float b) {
    __half2 h = __floats2half2_rn(a, b);
    return *(uint32_t*)&h;
}
__device__ __forceinline__ float hres(float a) {   // residual after fp16 rounding
    return a - __half2float(__float2half_rn(a));
}
__device__ __forceinline__ uint32_t swz(uint32_t o) { return o ^ ((o >> 3) & 0x70); }

// ---------------- prep 1: M = lb @ la  (rank-32 outer product) -----------
__global__ void __launch_bounds__(256) k_loramm(const float* __restrict__ lb,
                                                const float* __restrict__ la,
                                                float* __restrict__ M) {
    extern __shared__ float sm[];
    float* sla = sm;                 // 32*1024
    float* slb = sm + 32 * 1024;     // 16*32
    int l = blockIdx.x >> 6, ot = blockIdx.x & 63;
    const float* laL = la + (size_t)l * 32 * 1024;
    const float* lbL = lb + (size_t)l * 1024 * 32 + ot * 16 * 32;
    for (int i = threadIdx.x; i < 32 * 1024 / 4; i += 256)
        ((float4*)sla)[i] = ((const float4*)laL)[i];
    for (int i = threadIdx.x; i < 16 * 32 / 4; i += 256)
        ((float4*)slb)[i] = ((const float4*)lbL)[i];
    __syncthreads();
    float acc[16][4];
#pragma unroll
    for (int o = 0; o < 16; o++)
#pragma unroll
        for (int j = 0; j < 4; j++) acc[o][j] = 0.f;
    int i0 = threadIdx.x * 4;
#pragma unroll
    for (int r = 0; r < 32; r++) {
        float4 la4 = *(float4*)&sla[r * 1024 + i0];
#pragma unroll
        for (int o = 0; o < 16; o++) {
            float b = slb[o * 32 + r];
            acc[o][0] += b * la4.x; acc[o][1] += b * la4.y;
            acc[o][2] += b * la4.z; acc[o][3] += b * la4.w;
        }
    }
#pragma unroll
    for (int o = 0; o < 16; o++) {
        float4 v = {acc[o][0], acc[o][1], acc[o][2], acc[o][3]};
        *(float4*)&M[((size_t)l * 1024 + ot * 16 + o) * 1024 + i0] = v;
    }
}

// ---------------- prep 2: dequant + lora fold -> fp16 hi/lo --------------
__global__ void k_prepw(const int* __restrict__ q, const float* __restrict__ s,
                        const float* __restrict__ M) {
    int idx = blockIdx.x * 256 + threadIdx.x;     // over 6*1024*1024
    int i = idx & 1023, row = idx >> 10;          // row = l*1024 + o
    float w = ((float)q[idx] * (1.0f / 7.5f) - 1.0f) * s[(size_t)row * 64 + (i >> 4)]
            + M[idx];
    g_Wh[idx] = __float2half_rn(w);
    g_Wl[idx] = __float2half_rn(hres(w));
}

// x -> fp16 splits into buffer 0 (x itself used as block-0 residual)
__global__ void k_convert(const float* __restrict__ X) {
    int t = blockIdx.x * 256 + threadIdx.x;
    int m = t >> 8, c4 = (t & 255) * 4;
    float4 v = ((const float4*)X)[t];
    uint2 uh = {h2u(v.x, v.y), h2u(v.z, v.w)};
    uint2 ul = {h2u(hres(v.x), hres(v.y)), h2u(hres(v.z), hres(v.w))};
    *(uint2*)&g_Sh0[(size_t)m * DD + c4] = uh;
    *(uint2*)&g_Sl0[(size_t)m * DD + c4] = ul;
}

// ---------------- LayerNorm + exact GELU -> fp16 splits ------------------
__global__ void __launch_bounds__(256) k_lngelu(const float* __restrict__ Y,
                                                const float* __restrict__ g,
                                                const float* __restrict__ b,
                                                __half* __restrict__ oh,
                                                __half* __restrict__ ol) {
    int warp = threadIdx.x >> 5, lane = threadIdx.x & 31;
    int t = blockIdx.x * 8 + warp;
    const float4* row = (const float4*)(Y + (size_t)t * DD);
    float4 v[8];
    float s = 0.f, sq = 0.f;
#pragma unroll
    for (int i = 0; i < 8; i++) {
        v[i] = row[i * 32 + lane];
        s  += v[i].x + v[i].y + v[i].z + v[i].w;
        sq += v[i].x * v[i].x + v[i].y * v[i].y + v[i].z * v[i].z + v[i].w * v[i].w;
    }
#pragma unroll
    for (int o = 16; o > 0; o >>= 1) {
        s  += __shfl_xor_sync(0xffffffffu, s, o);
        sq += __shfl_xor_sync(0xffffffffu, sq, o);
    }
    float mu  = s * (1.f / 1024.f);
    float var = sq * (1.f / 1024.f) - mu * mu;
    float rs  = rsqrtf(var + 1e-5f);
#pragma unroll
    for (int i = 0; i < 8; i++) {
        int c4 = (i * 32 + lane) * 4;
        float xv[4] = {v[i].x, v[i].y, v[i].z, v[i].w};
        float yv[4];
#pragma unroll
        for (int j = 0; j < 4; j++) {
            float xn = (xv[j] - mu) * rs * g[c4 + j] + b[c4 + j];
            yv[j] = 0.5f * xn * (1.f + erff(xn * 0.70710678118654752f));
        }
        uint2 uh = {h2u(yv[0], yv[1]), h2u(yv[2], yv[3])};
        uint2 ul = {h2u(hres(yv[0]), hres(yv[1])), h2u(hres(yv[2]), hres(yv[3]))};
        *(uint2*)&oh[(size_t)t * DD + c4] = uh;
        *(uint2*)&ol[(size_t)t * DD + c4] = ul;
    }
}

// ------- MAIN GEMM: 512 thr, CTA 128x256, warp tile 64x32, 2-stage -------
// B-fragments register-double-buffered across kc to hide ldsm latency.
// MODE 0: dst = D + bias
// MODE 1: dst = D + bias + res, splits -> ShO/SlO
// MODE 2: dst = D + bias + res (no split write; final layer)
template <int MODE>
__global__ void __launch_bounds__(512, 1) k_gmain(
    const __half* __restrict__ Ah_g, const __half* __restrict__ Al_g,
    const __half* __restrict__ Bh_g, const __half* __restrict__ Bl_g,
    const float* __restrict__ bias, const float* __restrict__ res,
    float* __restrict__ dst,
    __half* __restrict__ ShO, __half* __restrict__ SlO)
{
    constexpr int NKT   = 16;
    constexpr int OF_AL = 16384;
    constexpr int OF_BH = 32768;
    constexpr int OF_BL = 65536;
    constexpr int STG   = 98304;
    constexpr int RB    = DD * 2;

    extern __shared__ char smem[];
    uint32_t ab = (s2u(smem) + 1023u) & ~1023u;

    int tid = threadIdx.x, wid = tid >> 5, lane = tid & 31;
    int n0 = blockIdx.x * 256;
    int m0 = blockIdx.y * 128;
    int wm = wid & 1, wn = wid >> 1;                    // 2 x 8 warps, 64x32 tiles

    auto ldst = [&](int kt, int s) {
        uint32_t base = ab + s * STG;
        size_t kb = (size_t)kt * 128;
        const char* pAh = (const char*)Ah_g + (size_t)m0 * RB + kb;
        const char* pAl = (const char*)Al_g + (size_t)m0 * RB + kb;
        const char* pBh = (const char*)Bh_g + (size_t)n0 * RB + kb;
        const char* pBl = (const char*)Bl_g + (size_t)n0 * RB + kb;
#pragma unroll
        for (int j = 0; j < 2; j++) {                   // A: 128 rows x 8 chunks
            int c = j * 512 + tid, row = c >> 3, qq = c & 7;
            uint32_t off = swz((uint32_t)(row * 128 + qq * 16));
            cpa(base + off, pAh + (size_t)row * RB + qq * 16);
            cpa(base + OF_AL + off, pAl + (size_t)row * RB + qq * 16);
        }
#pragma unroll
        for (int j = 0; j < 4; j++) {                   // B: 256 rows x 8 chunks
            int c = j * 512 + tid, row = c >> 3, qq = c & 7;
            uint32_t off = swz((uint32_t)(row * 128 + qq * 16));
            cpa(base + OF_BH + off, pBh + (size_t)row * RB + qq * 16);
            cpa(base + OF_BL + off, pBl + (size_t)row * RB + qq * 16);
        }
        asm volatile("cp.async.commit_group;" ::: "memory");
    };

    float acc[4][4][4];
#pragma unroll
    for (int i = 0; i < 4; i++)
#pragma unroll
        for (int j = 0; j < 4; j++)
#pragma unroll
            for (int q = 0; q < 4; q++) acc[i][j][q] = 0.f;

    uint32_t bh[2][4][2], bl[2][4][2];
    uint32_t aB = 0, bB = 0;

    // load B frags for kc into register buffer buf (compile-time buf via unroll)
    auto loadB = [&](int kc, int buf) {
        uint32_t nbyte = (uint32_t)(kc * 32 + (((lane >> 3) & 1) << 4));
#pragma unroll
        for (int nh = 0; nh < 2; nh++) {
            uint32_t nrow = (uint32_t)(wn * 32 + nh * 16 + ((lane >> 4) << 3) + (lane & 7));
            uint32_t off = swz(nrow * 128 + nbyte);
            uint32_t r[4];
            ldsm4(r, bB + off);
            bh[buf][nh * 2][0] = r[0]; bh[buf][nh * 2][1] = r[1];
            bh[buf][nh * 2 + 1][0] = r[2]; bh[buf][nh * 2 + 1][1] = r[3];
            ldsm4(r, aB + OF_BL + off);
            bl[buf][nh * 2][0] = r[0]; bl[buf][nh * 2][1] = r[1];
            bl[buf][nh * 2 + 1][0] = r[2]; bl[buf][nh * 2 + 1][1] = r[3];
        }
    };

    ldst(0, 0);

    for (int k = 0; k < NKT; k++) {
        const int s = k & 1;
        asm volatile("cp.async.wait_group 0;" ::: "memory");
        __syncthreads();
        aB = ab + s * STG;
        bB = aB + OF_BH;
        loadB(0, 0);                                    // frags for kc=0
        if (k + 1 < NKT) ldst(k + 1, s ^ 1);
#pragma unroll
        for (int kc = 0; kc < 4; kc++) {
            const int cur = kc & 1;
            if (kc < 3) loadB(kc + 1, cur ^ 1);         // overlap with MMA burst
            uint32_t abyte = (uint32_t)(kc * 32 + ((lane >> 4) << 4));
#pragma unroll
            for (int mg = 0; mg < 4; mg++) {
                uint32_t ah[4], al[4];
                uint32_t off = swz((uint32_t)((wm * 64 + mg * 16 + (lane & 15)) * 128) + abyte);
                ldsm4(ah, aB + off);
                ldsm4(al, aB + OF_AL + off);
#pragma unroll
                for (int ng = 0; ng < 4; ng++) {
                    mma_f32(acc[mg][ng], ah, bh[cur][ng]);
                    mma_f32(acc[mg][ng], ah, bl[cur][ng]);
                    mma_f32(acc[mg][ng], al, bh[cur][ng]);
                }
            }
        }
    }

    // ------------------------------- epilogue ----------------------------
    int t4 = lane >> 2, t2 = (lane & 3) * 2;
#pragma unroll
    for (int mg = 0; mg < 4; mg++)
#pragma unroll
        for (int ng = 0; ng < 4; ng++) {
            float* c = acc[mg][ng];
            int col = n0 + wn * 32 + ng * 8 + t2;
#pragma unroll
            for (int hh = 0; hh < 2; hh++) {
                int row = m0 + wm * 64 + mg * 16 + t4 + hh * 8;
                float2 b2 = *(const float2*)&bias[col];
                float v0 = c[hh * 2] + b2.x, v1 = c[hh * 2 + 1] + b2.y;
                if (MODE >= 1) {
                    float2 r2 = *(const float2*)&res[(size_t)row * DD + col];
                    v0 += r2.x; v1 += r2.y;
                }
                float2 o2 = {v0, v1};
                *(float2*)&dst[(size_t)row * DD + col] = o2;
                if (MODE == 1) {
                    *(uint32_t*)&ShO[(size_t)row * DD + col] = h2u(v0, v1);
                    *(uint32_t*)&SlO[(size_t)row * DD + col] = h2u(hres(v0), hres(v1));
                }
            }
        }
}

// ------------------------------- launch ----------------------------------
extern "C" void kernel_launch(void* const* d_in, const int* in_sizes, int n_in,
                              void* d_out, int out_size) {
    const float* x   = (const float*)d_in[0];
    const int*   q   = (const int*)d_in[1];
    const float* sc  = (const float*)d_in[2];
    const float* bia = (const float*)d_in[3];
    const float* la  = (const float*)d_in[4];
    const float* lbw = (const float*)d_in[5];
    const float* gam = (const float*)d_in[6];
    const float* bet = (const float*)d_in[7];
    float* out = (float*)d_out;

    __half *Wh, *Wl, *Sh[2], *Sl[2];
    float *H, *Y;
    cudaGetSymbolAddress((void**)&Wh, g_Wh);
    cudaGetSymbolAddress((void**)&Wl, g_Wl);
    cudaGetSymbolAddress((void**)&Sh[0], g_Sh0);
    cudaGetSymbolAddress((void**)&Sl[0], g_Sl0);
    cudaGetSymbolAddress((void**)&Sh[1], g_Sh1);
    cudaGetSymbolAddress((void**)&Sl[1], g_Sl1);
    cudaGetSymbolAddress((void**)&H,  g_H);
    cudaGetSymbolAddress((void**)&Y,  g_Y);

    const int SM_MAIN = 1024 + 2 * 98304;                 // 197632
    const int SM_MM   = (32 * 1024 + 16 * 32) * 4;        // 133120
    cudaFuncSetAttribute(k_gmain<0>, cudaFuncAttributeMaxDynamicSharedMemorySize, SM_MAIN);
    cudaFuncSetAttribute(k_gmain<1>, cudaFuncAttributeMaxDynamicSharedMemorySize, SM_MAIN);
    cudaFuncSetAttribute(k_gmain<2>, cudaFuncAttributeMaxDynamicSharedMemorySize, SM_MAIN);
    cudaFuncSetAttribute(k_loramm, cudaFuncAttributeMaxDynamicSharedMemorySize, SM_MM);

    k_loramm<<<6 * 64, 256, SM_MM>>>(lbw, la, Y);
    k_prepw<<<6 * DD * DD / 256, 256>>>(q, sc, Y);
    k_convert<<<MTOT * DD / 4 / 256, 256>>>(x);

    int p = 0;
    for (int blk = 0; blk < 3; ++blk) {
        int l0 = 2 * blk, l1 = 2 * blk + 1;
        k_gmain<0><<<dim3(4, MTOT / 128), 512, SM_MAIN>>>(
            Sh[p], Sl[p], Wh + (size_t)l0 * DD * DD, Wl + (size_t)l0 * DD * DD,
            bia + l0 * DD, nullptr, Y, nullptr, nullptr);
        k_lngelu<<<MTOT / 8, 256>>>(Y, gam + blk * DD, bet + blk * DD, Sh[p], Sl[p]);
        const float* resp = (blk == 0) ? x : H;
        if (blk == 2) {
            k_gmain<2><<<dim3(4, MTOT / 128), 512, SM_MAIN>>>(
                Sh[p], Sl[p], Wh + (size_t)l1 * DD * DD, Wl + (size_t)l1 * DD * DD,
                bia + l1 * DD, resp, out, nullptr, nullptr);
        } else {
            k_gmain<1><<<dim3(4, MTOT / 128), 512, SM_MAIN>>>(
                Sh[p], Sl[p], Wh + (size_t)l1 * DD * DD, Wl + (size_t)l1 * DD * DD,
                bia + l1 * DD, resp, H, Sh[p ^ 1], Sl[p ^ 1]);
        }
        p ^= 1;
    }
}

// round 17
// speedup vs baseline: 1.0874x; 1.0543x over previous
#include <cuda_runtime.h>
#include <cuda_fp16.h>
#include <math.h>
#include <stdint.h>

#define MTOT 32768
#define DD   1024

// ---------------- device scratch (no allocations allowed) ----------------
__device__ __align__(1024) __half g_Sh0[MTOT * DD];
__device__ __align__(1024) __half g_Sl0[MTOT * DD];
__device__ __align__(1024) __half g_Sh1[MTOT * DD];
__device__ __align__(1024) __half g_Sl1[MTOT * DD];
__device__ __align__(1024) __half g_Wh[6 * DD * DD];
__device__ __align__(1024) __half g_Wl[6 * DD * DD];
__device__ float g_H[MTOT * DD];
__device__ float g_Y[MTOT * DD];   // also reused as lb@la scratch during prep

// ------------------------------ helpers ----------------------------------
__device__ __forceinline__ uint32_t s2u(const void* p) {
    uint32_t a;
    asm("{ .reg .u64 t; cvta.to.shared.u64 t, %1; cvt.u32.u64 %0, t; }" : "=r"(a) : "l"(p));
    return a;
}
__device__ __forceinline__ void cpa(uint32_t s, const void* g) {
    asm volatile("cp.async.cg.shared.global [%0], [%1], 16;" :: "r"(s), "l"(g) : "memory");
}
__device__ __forceinline__ void ldsm4(uint32_t* r, uint32_t a) {
    asm volatile("ldmatrix.sync.aligned.m8n8.x4.shared.b16 {%0,%1,%2,%3}, [%4];"
                 : "=r"(r[0]), "=r"(r[1]), "=r"(r[2]), "=r"(r[3]) : "r"(a));
}
__device__ __forceinline__ void mma_f32(float* c, const uint32_t* a, const uint32_t* b) {
    asm volatile(
        "mma.sync.aligned.m16n8k16.row.col.f32.f16.f16.f32 "
        "{%0,%1,%2,%3}, {%4,%5,%6,%7}, {%8,%9}, {%0,%1,%2,%3};"
        : "+f"(c[0]), "+f"(c[1]), "+f"(c[2]), "+f"(c[3])
        : "r"(a[0]), "r"(a[1]), "r"(a[2]), "r"(a[3]), "r"(b[0]), "r"(b[1]));
}
__device__ __forceinline__ uint32_t h2u(float a, float b) {
    __half2 h = __floats2half2_rn(a, b);
    return *(uint32_t*)&h;
}
__device__ __forceinline__ float hres(float a) {   // residual after fp16 rounding
    return a - __half2float(__float2half_rn(a));
}
__device__ __forceinline__ uint32_t swz64(uint32_t o) { return o ^ ((o >> 3) & 0x30); }

// ---------------- prep 1: M = lb @ la  (rank-32 outer product) -----------
__global__ void __launch_bounds__(256) k_loramm(const float* __restrict__ lb,
                                                const float* __restrict__ la,
                                                float* __restrict__ M) {
    extern __shared__ float sm[];
    float* sla = sm;                 // 32*1024
    float* slb = sm + 32 * 1024;     // 16*32
    int l = blockIdx.x >> 6, ot = blockIdx.x & 63;
    const float* laL = la + (size_t)l * 32 * 1024;
    const float* lbL = lb + (size_t)l * 1024 * 32 + ot * 16 * 32;
    for (int i = threadIdx.x; i < 32 * 1024 / 4; i += 256)
        ((float4*)sla)[i] = ((const float4*)laL)[i];
    for (int i = threadIdx.x; i < 16 * 32 / 4; i += 256)
        ((float4*)slb)[i] = ((const float4*)lbL)[i];
    __syncthreads();
    float acc[16][4];
#pragma unroll
    for (int o = 0; o < 16; o++)
#pragma unroll
        for (int j = 0; j < 4; j++) acc[o][j] = 0.f;
    int i0 = threadIdx.x * 4;
#pragma unroll
    for (int r = 0; r < 32; r++) {
        float4 la4 = *(float4*)&sla[r * 1024 + i0];
#pragma unroll
        for (int o = 0; o < 16; o++) {
            float b = slb[o * 32 + r];
            acc[o][0] += b * la4.x; acc[o][1] += b * la4.y;
            acc[o][2] += b * la4.z; acc[o][3] += b * la4.w;
        }
    }
#pragma unroll
    for (int o = 0; o < 16; o++) {
        float4 v = {acc[o][0], acc[o][1], acc[o][2], acc[o][3]};
        *(float4*)&M[((size_t)l * 1024 + ot * 16 + o) * 1024 + i0] = v;
    }
}

// ---------------- prep 2: dequant + lora fold -> fp16 hi/lo --------------
__global__ void k_prepw(const int* __restrict__ q, const float* __restrict__ s,
                        const float* __restrict__ M) {
    int idx = blockIdx.x * 256 + threadIdx.x;     // over 6*1024*1024
    int i = idx & 1023, row = idx >> 10;          // row = l*1024 + o
    float w = ((float)q[idx] * (1.0f / 7.5f) - 1.0f) * s[(size_t)row * 64 + (i >> 4)]
            + M[idx];
    g_Wh[idx] = __float2half_rn(w);
    g_Wl[idx] = __float2half_rn(hres(w));
}

// x -> fp16 splits into buffer 0 (x itself used as block-0 residual)
__global__ void k_convert(const float* __restrict__ X) {
    int t = blockIdx.x * 256 + threadIdx.x;
    int m = t >> 8, c4 = (t & 255) * 4;
    float4 v = ((const float4*)X)[t];
    uint2 uh = {h2u(v.x, v.y), h2u(v.z, v.w)};
    uint2 ul = {h2u(hres(v.x), hres(v.y)), h2u(hres(v.z), hres(v.w))};
    *(uint2*)&g_Sh0[(size_t)m * DD + c4] = uh;
    *(uint2*)&g_Sl0[(size_t)m * DD + c4] = ul;
}

// ---------------- LayerNorm + exact GELU -> fp16 splits ------------------
__global__ void __launch_bounds__(256) k_lngelu(const float* __restrict__ Y,
                                                const float* __restrict__ g,
                                                const float* __restrict__ b,
                                                __half* __restrict__ oh,
                                                __half* __restrict__ ol) {
    int warp = threadIdx.x >> 5, lane = threadIdx.x & 31;
    int t = blockIdx.x * 8 + warp;
    const float4* row = (const float4*)(Y + (size_t)t * DD);
    float4 v[8];
    float s = 0.f, sq = 0.f;
#pragma unroll
    for (int i = 0; i < 8; i++) {
        v[i] = row[i * 32 + lane];
        s  += v[i].x + v[i].y + v[i].z + v[i].w;
        sq += v[i].x * v[i].x + v[i].y * v[i].y + v[i].z * v[i].z + v[i].w * v[i].w;
    }
#pragma unroll
    for (int o = 16; o > 0; o >>= 1) {
        s  += __shfl_xor_sync(0xffffffffu, s, o);
        sq += __shfl_xor_sync(0xffffffffu, sq, o);
    }
    float mu  = s * (1.f / 1024.f);
    float var = sq * (1.f / 1024.f) - mu * mu;
    float rs  = rsqrtf(var + 1e-5f);
#pragma unroll
    for (int i = 0; i < 8; i++) {
        int c4 = (i * 32 + lane) * 4;
        float xv[4] = {v[i].x, v[i].y, v[i].z, v[i].w};
        float yv[4];
#pragma unroll
        for (int j = 0; j < 4; j++) {
            float xn = (xv[j] - mu) * rs * g[c4 + j] + b[c4 + j];
            yv[j] = 0.5f * xn * (1.f + erff(xn * 0.70710678118654752f));
        }
        uint2 uh = {h2u(yv[0], yv[1]), h2u(yv[2], yv[3])};
        uint2 ul = {h2u(hres(yv[0]), hres(yv[1])), h2u(hres(yv[2]), hres(yv[3]))};
        *(uint2*)&oh[(size_t)t * DD + c4] = uh;
        *(uint2*)&ol[(size_t)t * DD + c4] = ul;
    }
}

// --- MAIN GEMM: 256 thr, CTA 128x128, BK=32 (SW64), 3-stage, 2 CTAs/SM ---
// D = A[128,1024] @ B[128,1024]^T, 3-term fp16 split, fp32 accum.
// MODE 0: dst = D + bias
// MODE 1: dst = D + bias + res, splits -> ShO/SlO
// MODE 2: dst = D + bias + res (no split write; final layer)
template <int MODE>
__global__ void __launch_bounds__(256, 2) k_gmain(
    const __half* __restrict__ Ah_g, const __half* __restrict__ Al_g,
    const __half* __restrict__ Bh_g, const __half* __restrict__ Bl_g,
    const float* __restrict__ bias, const float* __restrict__ res,
    float* __restrict__ dst,
    __half* __restrict__ ShO, __half* __restrict__ SlO)
{
    constexpr int NKT   = 32;           // 32 k-tiles of 32 (K = 1024)
    constexpr int OF_AL = 8192;
    constexpr int OF_BH = 16384;
    constexpr int OF_BL = 24576;
    constexpr int STG   = 32768;
    constexpr int RB    = DD * 2;       // gmem row bytes

    extern __shared__ char smem[];
    uint32_t ab = (s2u(smem) + 1023u) & ~1023u;

    int tid = threadIdx.x, wid = tid >> 5, lane = tid & 31;
    int n0 = blockIdx.x * 128;
    int m0 = blockIdx.y * 128;
    int wm = wid & 1, wn = wid >> 1;                    // 2 x 4 warps, 64x32 tiles

    auto ldst = [&](int kt, int s) {
        uint32_t base = ab + s * STG;
        size_t kb = (size_t)kt * 64;
        const char* pAh = (const char*)Ah_g + (size_t)m0 * RB + kb;
        const char* pAl = (const char*)Al_g + (size_t)m0 * RB + kb;
        const char* pBh = (const char*)Bh_g + (size_t)n0 * RB + kb;
        const char* pBl = (const char*)Bl_g + (size_t)n0 * RB + kb;
#pragma unroll
        for (int j = 0; j < 2; j++) {                   // 128 rows x 4 chunks
            int c = j * 256 + tid, row = c >> 2, qq = c & 3;
            uint32_t off = swz64((uint32_t)(row * 64 + qq * 16));
            cpa(base + off,         pAh + (size_t)row * RB + qq * 16);
            cpa(base + OF_AL + off, pAl + (size_t)row * RB + qq * 16);
            cpa(base + OF_BH + off, pBh + (size_t)row * RB + qq * 16);
            cpa(base + OF_BL + off, pBl + (size_t)row * RB + qq * 16);
        }
        asm volatile("cp.async.commit_group;" ::: "memory");
    };

    float acc[4][4][4];
#pragma unroll
    for (int i = 0; i < 4; i++)
#pragma unroll
        for (int j = 0; j < 4; j++)
#pragma unroll
            for (int q = 0; q < 4; q++) acc[i][j][q] = 0.f;

    uint32_t bh[2][4][2], bl[2][4][2];
    uint32_t aB = 0, bB = 0;

    auto loadB = [&](int kc, int buf) {
        uint32_t nbyte = (uint32_t)(kc * 32 + (((lane >> 3) & 1) << 4));
#pragma unroll
        for (int nh = 0; nh < 2; nh++) {
            uint32_t nrow = (uint32_t)(wn * 32 + nh * 16 + ((lane >> 4) << 3) + (lane & 7));
            uint32_t off = swz64(nrow * 64 + nbyte);
            uint32_t r[4];
            ldsm4(r, bB + off);
            bh[buf][nh * 2][0] = r[0]; bh[buf][nh * 2][1] = r[1];
            bh[buf][nh * 2 + 1][0] = r[2]; bh[buf][nh * 2 + 1][1] = r[3];
            ldsm4(r, aB + OF_BL + off);
            bl[buf][nh * 2][0] = r[0]; bl[buf][nh * 2][1] = r[1];
            bl[buf][nh * 2 + 1][0] = r[2]; bl[buf][nh * 2 + 1][1] = r[3];
        }
    };

    ldst(0, 0); ldst(1, 1);

    for (int k = 0; k < NKT; k++) {
        const int s = k % 3;
        asm volatile("cp.async.wait_group 1;" ::: "memory");
        __syncthreads();
        aB = ab + s * STG;
        bB = aB + OF_BH;
        loadB(0, 0);
        if (k + 2 < NKT) ldst(k + 2, (k + 2) % 3);
#pragma unroll
        for (int kc = 0; kc < 2; kc++) {
            const int cur = kc & 1;
            if (kc == 0) loadB(1, 1);                   // overlap with MMA burst
            uint32_t abyte = (uint32_t)(kc * 32 + ((lane >> 4) << 4));
#pragma unroll
            for (int mg = 0; mg < 4; mg++) {
                uint32_t ah[4], al[4];
                uint32_t off = swz64((uint32_t)((wm * 64 + mg * 16 + (lane & 15)) * 64) + abyte);
                ldsm4(ah, aB + off);
                ldsm4(al, aB + OF_AL + off);
#pragma unroll
                for (int ng = 0; ng < 4; ng++) {
                    mma_f32(acc[mg][ng], ah, bh[cur][ng]);
                    mma_f32(acc[mg][ng], ah, bl[cur][ng]);
                    mma_f32(acc[mg][ng], al, bh[cur][ng]);
                }
            }
        }
    }

    // ------------------------------- epilogue ----------------------------
    int t4 = lane >> 2, t2 = (lane & 3) * 2;
#pragma unroll
    for (int mg = 0; mg < 4; mg++)
#pragma unroll
        for (int ng = 0; ng < 4; ng++) {
            float* c = acc[mg][ng];
            int col = n0 + wn * 32 + ng * 8 + t2;
#pragma unroll
            for (int hh = 0; hh < 2; hh++) {
                int row = m0 + wm * 64 + mg * 16 + t4 + hh * 8;
                float2 b2 = *(const float2*)&bias[col];
                float v0 = c[hh * 2] + b2.x, v1 = c[hh * 2 + 1] + b2.y;
                if (MODE >= 1) {
                    float2 r2 = *(const float2*)&res[(size_t)row * DD + col];
                    v0 += r2.x; v1 += r2.y;
                }
                float2 o2 = {v0, v1};
                *(float2*)&dst[(size_t)row * DD + col] = o2;
                if (MODE == 1) {
                    *(uint32_t*)&ShO[(size_t)row * DD + col] = h2u(v0, v1);
                    *(uint32_t*)&SlO[(size_t)row * DD + col] = h2u(hres(v0), hres(v1));
                }
            }
        }
}

// ------------------------------- launch ----------------------------------
extern "C" void kernel_launch(void* const* d_in, const int* in_sizes, int n_in,
                              void* d_out, int out_size) {
    const float* x   = (const float*)d_in[0];
    const int*   q   = (const int*)d_in[1];
    const float* sc  = (const float*)d_in[2];
    const float* bia = (const float*)d_in[3];
    const float* la  = (const float*)d_in[4];
    const float* lbw = (const float*)d_in[5];
    const float* gam = (const float*)d_in[6];
    const float* bet = (const float*)d_in[7];
    float* out = (float*)d_out;

    __half *Wh, *Wl, *Sh[2], *Sl[2];
    float *H, *Y;
    cudaGetSymbolAddress((void**)&Wh, g_Wh);
    cudaGetSymbolAddress((void**)&Wl, g_Wl);
    cudaGetSymbolAddress((void**)&Sh[0], g_Sh0);
    cudaGetSymbolAddress((void**)&Sl[0], g_Sl0);
    cudaGetSymbolAddress((void**)&Sh[1], g_Sh1);
    cudaGetSymbolAddress((void**)&Sl[1], g_Sl1);
    cudaGetSymbolAddress((void**)&H,  g_H);
    cudaGetSymbolAddress((void**)&Y,  g_Y);

    const int SM_MAIN = 1024 + 3 * 32768;                 // 99328 (<= 113KB for 2 CTA/SM)
    const int SM_MM   = (32 * 1024 + 16 * 32) * 4;        // 133120
    cudaFuncSetAttribute(k_gmain<0>, cudaFuncAttributeMaxDynamicSharedMemorySize, SM_MAIN);
    cudaFuncSetAttribute(k_gmain<1>, cudaFuncAttributeMaxDynamicSharedMemorySize, SM_MAIN);
    cudaFuncSetAttribute(k_gmain<2>, cudaFuncAttributeMaxDynamicSharedMemorySize, SM_MAIN);
    cudaFuncSetAttribute(k_loramm, cudaFuncAttributeMaxDynamicSharedMemorySize, SM_MM);

    k_loramm<<<6 * 64, 256, SM_MM>>>(lbw, la, Y);
    k_prepw<<<6 * DD * DD / 256, 256>>>(q, sc, Y);
    k_convert<<<MTOT * DD / 4 / 256, 256>>>(x);

    int p = 0;
    for (int blk = 0; blk < 3; ++blk) {
        int l0 = 2 * blk, l1 = 2 * blk + 1;
        k_gmain<0><<<dim3(8, MTOT / 128), 256, SM_MAIN>>>(
            Sh[p], Sl[p], Wh + (size_t)l0 * DD * DD, Wl + (size_t)l0 * DD * DD,
            bia + l0 * DD, nullptr, Y, nullptr, nullptr);
        k_lngelu<<<MTOT / 8, 256>>>(Y, gam + blk * DD, bet + blk * DD, Sh[p], Sl[p]);
        const float* resp = (blk == 0) ? x : H;
        if (blk == 2) {
            k_gmain<2><<<dim3(8, MTOT / 128), 256, SM_MAIN>>>(
                Sh[p], Sl[p], Wh + (size_t)l1 * DD * DD, Wl + (size_t)l1 * DD * DD,
                bia + l1 * DD, resp, out, nullptr, nullptr);
        } else {
            k_gmain<1><<<dim3(8, MTOT / 128), 256, SM_MAIN>>>(
                Sh[p], Sl[p], Wh + (size_t)l1 * DD * DD, Wl + (size_t)l1 * DD * DD,
                bia + l1 * DD, resp, H, Sh[p ^ 1], Sl[p ^ 1]);
        }
        p ^= 1;
    }
}